// round 1
// baseline (speedup 1.0000x reference)
#include <cuda_runtime.h>
#include <cstddef>

// Problem constants
#define BB 64
#define SS 2048
#define II 64
#define HH 128

// 64 MB scratch for the precomputed input projection wx = X @ W (reused by both layers)
__device__ float g_wx[BB * SS * HH];

// ---------------- packed f32x2 helpers ----------------
__device__ __forceinline__ unsigned long long ffma2(unsigned long long a,
                                                    unsigned long long b,
                                                    unsigned long long c) {
    unsigned long long d;
    asm("fma.rn.f32x2 %0, %1, %2, %3;" : "=l"(d) : "l"(a), "l"(b), "l"(c));
    return d;
}
__device__ __forceinline__ unsigned long long fadd2(unsigned long long a,
                                                    unsigned long long b) {
    unsigned long long d;
    asm("add.rn.f32x2 %0, %1, %2;" : "=l"(d) : "l"(a), "l"(b));
    return d;
}
__device__ __forceinline__ void unpack2(unsigned long long s, float& lo, float& hi) {
    asm("mov.b64 {%0, %1}, %2;" : "=f"(lo), "=f"(hi) : "l"(s));
}

__device__ __forceinline__ float sigmf(float x) {
    return __fdividef(1.0f, 1.0f + __expf(-x));
}
__device__ __forceinline__ float tanhf_fast(float x) {
    x = fminf(fmaxf(x, -15.0f), 15.0f);
    float e = __expf(-2.0f * x);
    return __fdividef(1.0f - e, 1.0f + e);
}

// ---------------- GEMM: Y[M,128] = X[M,K] @ W[K,128], Y = g_wx ----------------
// 128 threads. Thread t: column pair p = t>>1 -> cols (2p, 2p+1); half = t&1 owns
// k-range [half*K/2, half*K/2 + K/2). W column-pairs live in registers (f32x2).
// X rows staged duplicated ({v,v}) in SMEM so the inner loop is LDS.128 + 2x FFMA2.
// After the k-split, a shfl.bfly(1) reduce leaves thread t holding column t.
template <int K>
__global__ void __launch_bounds__(128, 2)
gemm_wx_kernel(const float* __restrict__ X, const float* __restrict__ W,
               int rows_per_cta) {
    constexpr int KH = K / 2;
    constexpr int CHUNK = 32;
    __shared__ __align__(16) float2 xs[CHUNK][K + 4];  // halves at 0 and KH+2 (bank-disjoint)

    const int tid = threadIdx.x;
    const int p = tid >> 1;
    const int half = tid & 1;

    unsigned long long wreg[KH];
#pragma unroll
    for (int k = 0; k < KH; k++) {
        wreg[k] = *reinterpret_cast<const unsigned long long*>(
            W + (size_t)(half * KH + k) * HH + 2 * p);
    }

    const int row0 = blockIdx.x * rows_per_cta;

    for (int rc = 0; rc < rows_per_cta; rc += CHUNK) {
        __syncthreads();  // previous chunk reads complete
        // stage CHUNK rows, duplicated
        for (int idx = tid; idx < CHUNK * K; idx += 128) {
            int r = idx / K;
            int k = idx % K;
            float v = X[(size_t)(row0 + rc + r) * K + k];
            int slot = (k < KH) ? k : (k + 2);
            xs[r][slot] = make_float2(v, v);
        }
        __syncthreads();

#pragma unroll 2
        for (int r = 0; r < CHUNK; r++) {
            const ulonglong2* xp =
                reinterpret_cast<const ulonglong2*>(&xs[r][half * (KH + 2)]);
            unsigned long long a0 = 0, a1 = 0, a2 = 0, a3 = 0;
#pragma unroll
            for (int i = 0; i < KH / 2; i++) {
                ulonglong2 v = xp[i];
                if (i & 1) {
                    a2 = ffma2(v.x, wreg[2 * i], a2);
                    a3 = ffma2(v.y, wreg[2 * i + 1], a3);
                } else {
                    a0 = ffma2(v.x, wreg[2 * i], a0);
                    a1 = ffma2(v.y, wreg[2 * i + 1], a1);
                }
            }
            unsigned long long s = fadd2(fadd2(a0, a2), fadd2(a1, a3));
            float lo, hi;
            unpack2(s, lo, hi);
            float olo = __shfl_xor_sync(0xffffffffu, lo, 1);
            float ohi = __shfl_xor_sync(0xffffffffu, hi, 1);
            float y = half ? (hi + ohi) : (lo + olo);
            g_wx[(size_t)(row0 + rc + r) * HH + tid] = y;
        }
    }
}

// ---------------- Recurrent scan (one CTA per batch row) ----------------
// pre[b,j,t] = wx[b,t,j] + sum_k h[b,k] * u[k,j]
// z = sigmoid(pre+bg); hh = tanh(pre+bu);
// h = gc*(z*h + (sz*(1-z)+sn)*hh) + (1-gc)*lambda
// Thread t: pair p=t>>1, half=t&1; u column-pairs in regs; duplicated-h ping-pong
// in SMEM; 4-deep LDG prefetch ring for wx; one __syncthreads per step.
__global__ void __launch_bounds__(128, 1)
scan_kernel(const float* __restrict__ u, const float* __restrict__ bg,
            const float* __restrict__ bu, const float* __restrict__ zeta,
            const float* __restrict__ nu, const float* __restrict__ lambd,
            const float* __restrict__ gamma, float* __restrict__ out,
            float* __restrict__ hT) {
    const int b = blockIdx.x;
    const int tid = threadIdx.x;
    const int p = tid >> 1;
    const int half = tid & 1;
    const int kbase = half * 64;

    __shared__ __align__(16) float2 hbuf[2][2][66];  // [pingpong][k-half][slot]

    unsigned long long ureg[64];
#pragma unroll
    for (int kk = 0; kk < 64; kk++) {
        ureg[kk] = *reinterpret_cast<const unsigned long long*>(
            u + (size_t)(kbase + kk) * HH + 2 * p);
    }

    const float bgj = bg[tid];
    const float buj = bu[tid];
    const float sz = sigmf(zeta[0]);
    const float sn = sigmf(nu[0]);
    const float gc = fminf(fmaxf(gamma[0], 0.0f), 1.0f);
    const float omgl = (1.0f - gc) * lambd[0];

    hbuf[0][tid >> 6][tid & 63] = make_float2(0.0f, 0.0f);
    float h_old = 0.0f;

    const float* wxb = g_wx + (size_t)b * SS * HH + tid;
    float* outb = out + (size_t)b * SS * HH + tid;

    float ring[4];
#pragma unroll
    for (int i = 0; i < 4; i++) ring[i] = wxb[i * HH];

    __syncthreads();

    int buf = 0;
#pragma unroll 4
    for (int s = 0; s < SS; s++) {
        float wxv = ring[s & 3];
        if (s + 4 < SS) ring[s & 3] = __ldg(wxb + (size_t)(s + 4) * HH);

        const ulonglong2* hp =
            reinterpret_cast<const ulonglong2*>(&hbuf[buf][half][0]);
        unsigned long long a0 = 0, a1 = 0, a2 = 0, a3 = 0;
#pragma unroll
        for (int i = 0; i < 32; i++) {
            ulonglong2 v = hp[i];
            if (i & 1) {
                a2 = ffma2(v.x, ureg[2 * i], a2);
                a3 = ffma2(v.y, ureg[2 * i + 1], a3);
            } else {
                a0 = ffma2(v.x, ureg[2 * i], a0);
                a1 = ffma2(v.y, ureg[2 * i + 1], a1);
            }
        }
        unsigned long long ssum = fadd2(fadd2(a0, a2), fadd2(a1, a3));
        float lo, hi;
        unpack2(ssum, lo, hi);
        float olo = __shfl_xor_sync(0xffffffffu, lo, 1);
        float ohi = __shfl_xor_sync(0xffffffffu, hi, 1);
        float pre = (half ? (hi + ohi) : (lo + olo)) + wxv;

        float z = sigmf(pre + bgj);
        float hh = tanhf_fast(pre + buj);
        float hnew = z * h_old + (sz * (1.0f - z) + sn) * hh;
        float hc = gc * hnew + omgl;
        h_old = hc;

        outb[(size_t)s * HH] = hc;
        hbuf[buf ^ 1][tid >> 6][tid & 63] = make_float2(hc, hc);
        __syncthreads();
        buf ^= 1;
    }

    hT[b * HH + tid] = h_old;
}

// ---------------- launch ----------------
extern "C" void kernel_launch(void* const* d_in, const int* in_sizes, int n_in,
                              void* d_out, int out_size) {
    const float* x      = (const float*)d_in[0];
    const float* w0     = (const float*)d_in[1];
    const float* u0     = (const float*)d_in[2];
    const float* bg0    = (const float*)d_in[3];
    const float* bu0    = (const float*)d_in[4];
    const float* zeta0  = (const float*)d_in[5];
    const float* nu0    = (const float*)d_in[6];
    const float* lambd0 = (const float*)d_in[7];
    const float* gamma0 = (const float*)d_in[8];
    const float* w1     = (const float*)d_in[9];
    const float* u1     = (const float*)d_in[10];
    const float* bg1    = (const float*)d_in[11];
    const float* bu1    = (const float*)d_in[12];
    const float* zeta1  = (const float*)d_in[13];
    const float* nu1    = (const float*)d_in[14];
    const float* lambd1 = (const float*)d_in[15];
    const float* gamma1 = (const float*)d_in[16];

    float* out = (float*)d_out;                  // out1 region [B*S*H]
    float* h0T = out + (size_t)BB * SS * HH;     // h_n[0]
    float* h1T = h0T + (size_t)BB * HH;          // h_n[1]

    const int M = BB * SS;       // 131072 rows
    const int GRID = 1024;
    const int RPC = M / GRID;    // 128 rows per CTA

    // Layer 0: wx0 = x @ w0 -> g_wx ; scan0 -> out (as out0 scratch) + h0T
    gemm_wx_kernel<II><<<GRID, 128>>>(x, w0, RPC);
    scan_kernel<<<BB, 128>>>(u0, bg0, bu0, zeta0, nu0, lambd0, gamma0, out, h0T);

    // Layer 1: wx1 = out0 @ w1 -> g_wx ; scan1 -> out (final) + h1T
    gemm_wx_kernel<HH><<<GRID, 128>>>(out, w1, RPC);
    scan_kernel<<<BB, 128>>>(u1, bg1, bu1, zeta1, nu1, lambd1, gamma1, out, h1T);
}